// round 13
// baseline (speedup 1.0000x reference)
#include <cuda_runtime.h>
#include <cuda_bf16.h>
#include <cuda_fp16.h>
#include <cuda_fp8.h>
#include <cstdint>
#include <math.h>

#define DINLINE __device__ __forceinline__

// ---------------- static scratch (no allocations allowed) ----------------
#define MAXM 16384
#define MAXK 2048
#define MAXN 2048
__device__ uint8_t g_aq[(size_t)MAXM * MAXK];            // quantized activations, raw e4m3 bytes
__device__ float   g_as[(size_t)MAXM * (MAXK/128)];
__device__ uint8_t g_wq[(size_t)MAXN * MAXK];            // quantized weights, raw e4m3 bytes
__device__ float   g_ws[(size_t)(MAXN/128) * (MAXK/128)];

// ---------------- helpers ----------------
DINLINE uint32_t smem_u32(const void* p) {
    uint32_t a;
    asm("{ .reg .u64 t; cvta.to.shared.u64 t, %1; cvt.u32.u64 %0, t; }" : "=r"(a) : "l"(p));
    return a;
}
DINLINE void cp_async16(uint32_t dst, const void* src) {
    asm volatile("cp.async.cg.shared.global [%0], [%1], 16;" :: "r"(dst), "l"(src));
}
DINLINE void cp_commit() { asm volatile("cp.async.commit_group;" ::: "memory"); }
template <int N> DINLINE void cp_wait_group() {
    asm volatile("cp.async.wait_group %0;" :: "n"(N) : "memory");
}
DINLINE uint32_t lds32(uint32_t addr) {
    uint32_t v;
    asm volatile("ld.shared.b32 %0, [%1];" : "=r"(v) : "r"(addr));
    return v;
}
// fp8 e4m3 x e4m3 -> fp32 MMA, m16n8k32 (baseline PTX since sm_89)
DINLINE void mma_fp8(float* c, const uint32_t* a, uint32_t b0, uint32_t b1) {
    asm volatile(
        "mma.sync.aligned.m16n8k32.row.col.f32.e4m3.e4m3.f32 "
        "{%0,%1,%2,%3}, {%4,%5,%6,%7}, {%8,%9}, {%0,%1,%2,%3};"
        : "+f"(c[0]), "+f"(c[1]), "+f"(c[2]), "+f"(c[3])
        : "r"(a[0]), "r"(a[1]), "r"(a[2]), "r"(a[3]), "r"(b0), "r"(b1));
}

// pack 4 floats -> 4 e4m3 bytes via paired converts (x -> byte 0)  [proven R10]
DINLINE uint32_t fp8_pack4(float x, float y, float z, float w) {
    uint32_t lo = __nv_cvt_float2_to_fp8x2(make_float2(x, y), __NV_SATFINITE, __NV_E4M3);
    uint32_t hi = __nv_cvt_float2_to_fp8x2(make_float2(z, w), __NV_SATFINITE, __NV_E4M3);
    return lo | (hi << 16);
}

// ---------------- kernel 1: rowwise activation quantization (R10 — best measured) ----------------
__global__ void quant_act_kernel(const float* __restrict__ x, int M, int KB) {
    int warp = blockIdx.x * (blockDim.x >> 5) + (threadIdx.x >> 5);
    int lane = threadIdx.x & 31;
    int nPairs = (M * KB) >> 1;
    if (warp >= nPairs) return;
    int blk = (warp << 1) + (lane >> 4);
    int m = blk / KB, kb = blk - m * KB;
    int K = KB << 7;
    int l = lane & 15;
    const float* base = x + (size_t)m * K + (kb << 7) + (l << 3);
    float4 v0 = *reinterpret_cast<const float4*>(base);
    float4 v1 = *reinterpret_cast<const float4*>(base + 4);

    float amax = fmaxf(fmaxf(fabsf(v0.x), fabsf(v0.y)), fmaxf(fabsf(v0.z), fabsf(v0.w)));
    amax = fmaxf(amax, fmaxf(fmaxf(fabsf(v1.x), fabsf(v1.y)), fmaxf(fabsf(v1.z), fabsf(v1.w))));
#pragma unroll
    for (int o = 8; o > 0; o >>= 1) amax = fmaxf(amax, __shfl_xor_sync(0xffffffffu, amax, o));
    amax = fmaxf(amax, 1e-4f);
    float scale = amax / 448.0f;
    float inv = 1.0f / scale;

    uint2 packed;
    packed.x = fp8_pack4(v0.x * inv, v0.y * inv, v0.z * inv, v0.w * inv);
    packed.y = fp8_pack4(v1.x * inv, v1.y * inv, v1.z * inv, v1.w * inv);
    *reinterpret_cast<uint2*>(g_aq + (size_t)m * K + (kb << 7) + (l << 3)) = packed;
    if (l == 0) g_as[(size_t)m * KB + kb] = scale;
}

// ---------------- kernel 2: 128x128 blockwise weight quantization (R10) ----------------
__global__ void quant_w_kernel(const float* __restrict__ w, int N, int KB) {
    int kb = blockIdx.x, nb = blockIdx.y;
    int K = KB << 7;
    int tid = threadIdx.x;  // 256
    const float* base = w + (size_t)(nb * 128) * K + (kb << 7);
    float4 v[16];
    float amax = 0.f;
#pragma unroll
    for (int j = 0; j < 16; j++) {
        int chunk = tid + j * 256;
        int row = chunk >> 5;
        int col4 = chunk & 31;
        v[j] = *reinterpret_cast<const float4*>(base + (size_t)row * K + col4 * 4);
        amax = fmaxf(amax, fmaxf(fmaxf(fabsf(v[j].x), fabsf(v[j].y)),
                                 fmaxf(fabsf(v[j].z), fabsf(v[j].w))));
    }
    __shared__ float red[8];
#pragma unroll
    for (int o = 16; o > 0; o >>= 1) amax = fmaxf(amax, __shfl_xor_sync(0xffffffffu, amax, o));
    if ((tid & 31) == 0) red[tid >> 5] = amax;
    __syncthreads();
    if (tid == 0) {
        float m = red[0];
#pragma unroll
        for (int i = 1; i < 8; i++) m = fmaxf(m, red[i]);
        m = fmaxf(m, 1e-4f);
        float s = m / 448.0f;
        red[0] = s;
        g_ws[(size_t)nb * KB + kb] = s;
    }
    __syncthreads();
    float inv = 1.0f / red[0];
#pragma unroll
    for (int j = 0; j < 16; j++) {
        int chunk = tid + j * 256;
        int row = chunk >> 5;
        int col4 = chunk & 31;
        uint32_t packed = fp8_pack4(v[j].x * inv, v[j].y * inv, v[j].z * inv, v[j].w * inv);
        *reinterpret_cast<uint32_t*>(g_wq + (size_t)(nb * 128 + row) * K + (kb << 7) + col4 * 4) = packed;
    }
}

// ---------------- kernel 3: fp8 mma.sync GEMM, 2 CTAs/SM, 4 stages ----------------
// CTA tile 128(M) x 64(N), BK=128 bytes, STAGES=4, smem 110,592 B/CTA
// (2 x 110,592 = 221,184 <= 228KB/SM -> still 2 CTAs/SM).
// 8 warps as 4(M) x 2(N), warp tile 32x32. Promote-scale LDGs hoisted to the
// top of each iteration so their ~250-cyc L2 latency hides behind the kk loop.

#define BM 128
#define BN 64
#define BKB 128                                   // K-bytes per iteration
#define STAGES 4
#define RSTRIDE 144
#define TILE_A (128 * RSTRIDE)                    // 18432
#define TILE_B (64 * RSTRIDE)                     // 9216
#define STAGE_BYTES (TILE_A + TILE_B)             // 27648
#define SMEM_TOTAL (STAGES * STAGE_BYTES)         // 110592

DINLINE void load_stage(uint32_t sA, uint32_t sB,
                        const uint8_t* gA, const uint8_t* gB,
                        int K, int tid) {
#pragma unroll
    for (int i = 0; i < 4; i++) {
        int c = tid + i * 256;                 // 1024 chunks of 16B (A: 128 rows)
        int row = c >> 3;
        int cir = c & 7;
        cp_async16(sA + (uint32_t)(row * RSTRIDE + cir * 16),
                   (const void*)(gA + (size_t)row * K + (cir << 4)));
    }
#pragma unroll
    for (int i = 0; i < 2; i++) {
        int c = tid + i * 256;                 // 512 chunks (B: 64 rows)
        int row = c >> 3;
        int cir = c & 7;
        cp_async16(sB + (uint32_t)(row * RSTRIDE + cir * 16),
                   (const void*)(gB + (size_t)row * K + (cir << 4)));
    }
}

__global__ void __launch_bounds__(256, 2)
gemm_kernel(float* __restrict__ out, int M, int N, int K) {
    extern __shared__ __align__(128) unsigned char dynsmem[];
    const int KB  = K >> 7;        // scale blocks == iterations (BK=128)
    const int tid = threadIdx.x;
    const int wid = tid >> 5;
    const int lane = tid & 31;
    const int wm = wid >> 1;       // 0..3  (M)
    const int wn = wid & 1;        // 0..1  (N)
    const int nb = blockIdx.x, mb = blockIdx.y;
    const int m0 = mb << 7, n0 = nb << 6;

    uint32_t sbase = smem_u32(dynsmem);
    const uint8_t* gA = g_aq + (size_t)m0 * K;
    const uint8_t* gB = g_wq + (size_t)n0 * K;

    float accf[2][4][4];
#pragma unroll
    for (int i = 0; i < 2; i++)
#pragma unroll
        for (int j = 0; j < 4; j++)
#pragma unroll
            for (int q = 0; q < 4; q++) accf[i][j][q] = 0.f;

    const int g  = lane >> 2;      // fragment row group 0..7
    const int cc = lane & 3;       // fragment k chunk 0..3 (4 bytes each)
    const uint32_t fragOff = (uint32_t)(g * RSTRIDE + cc * 4);

    uint32_t aBase[2], bBase[4];
#pragma unroll
    for (int mf = 0; mf < 2; mf++) aBase[mf] = (uint32_t)(((wm << 5) + (mf << 4)) * RSTRIDE) + fragOff;
#pragma unroll
    for (int nf = 0; nf < 4; nf++) bBase[nf] = (uint32_t)(((wn << 5) + (nf << 3)) * RSTRIDE) + fragOff;

    // prologue: fill stages 0..2
#pragma unroll
    for (int s = 0; s < STAGES - 1; s++) {
        load_stage(sbase + s * STAGE_BYTES, sbase + s * STAGE_BYTES + TILE_A,
                   gA + (size_t)s * BKB, gB + (size_t)s * BKB, K, tid);
        cp_commit();
    }

    const float* wsp = g_ws + (size_t)(n0 >> 7) * KB;
    const int rA0 = m0 + (wm << 5) + g;
    const float* asp0 = g_as + (size_t)rA0 * KB;
    const float* asp1 = g_as + (size_t)(rA0 + 8) * KB;
    const float* asp2 = g_as + (size_t)(rA0 + 16) * KB;
    const float* asp3 = g_as + (size_t)(rA0 + 24) * KB;

    for (int it = 0; it < KB; ++it) {
        cp_wait_group<STAGES - 2>();
        __syncthreads();

        // hoisted scale loads: latency hidden behind the kk loop below
        float ws  = __ldg(wsp + it);
        float a0s = __ldg(asp0 + it);
        float a1s = __ldg(asp1 + it);
        float a2s = __ldg(asp2 + it);
        float a3s = __ldg(asp3 + it);

        int pf = it + STAGES - 1;
        if (pf < KB) {
            int s = pf & (STAGES - 1);
            load_stage(sbase + s * STAGE_BYTES, sbase + s * STAGE_BYTES + TILE_A,
                       gA + (size_t)pf * BKB, gB + (size_t)pf * BKB, K, tid);
        }
        cp_commit();

        uint32_t stA = sbase + (it & (STAGES - 1)) * STAGE_BYTES;
        uint32_t stB = stA + TILE_A;

        float accp[2][4][4];
#pragma unroll
        for (int i = 0; i < 2; i++)
#pragma unroll
            for (int j = 0; j < 4; j++)
#pragma unroll
                for (int q = 0; q < 4; q++) accp[i][j][q] = 0.f;

#pragma unroll
        for (int kk = 0; kk < 4; kk++) {               // 4 x k32 = 128 K-bytes
            const uint32_t kOff = (uint32_t)(kk * 32);
            uint32_t a[2][4];
#pragma unroll
            for (int mf = 0; mf < 2; mf++) {
                uint32_t p = stA + aBase[mf] + kOff;
                a[mf][0] = lds32(p);                    // A[g   ][4c..4c+3]
                a[mf][1] = lds32(p + 8 * RSTRIDE);      // A[g+8 ][4c..4c+3]
                a[mf][2] = lds32(p + 16);               // A[g   ][16+4c..]
                a[mf][3] = lds32(p + 8 * RSTRIDE + 16); // A[g+8 ][16+4c..]
            }
            uint32_t b[4][2];
#pragma unroll
            for (int nf = 0; nf < 4; nf++) {
                uint32_t p = stB + bBase[nf] + kOff;
                b[nf][0] = lds32(p);                    // W[n][4c..4c+3]
                b[nf][1] = lds32(p + 16);               // W[n][16+4c..]
            }
#pragma unroll
            for (int mf = 0; mf < 2; mf++)
#pragma unroll
                for (int nf = 0; nf < 4; nf++)
                    mma_fp8(accp[mf][nf], a[mf], b[nf][0], b[nf][1]);
        }

        // promote this 128-K block: accf += (a_s[row]*w_s) * accp
        {
            float s0 = a0s * ws, s1 = a1s * ws, s2 = a2s * ws, s3 = a3s * ws;
#pragma unroll
            for (int nf = 0; nf < 4; nf++) {
                accf[0][nf][0] = fmaf(s0, accp[0][nf][0], accf[0][nf][0]);
                accf[0][nf][1] = fmaf(s0, accp[0][nf][1], accf[0][nf][1]);
                accf[0][nf][2] = fmaf(s1, accp[0][nf][2], accf[0][nf][2]);
                accf[0][nf][3] = fmaf(s1, accp[0][nf][3], accf[0][nf][3]);
                accf[1][nf][0] = fmaf(s2, accp[1][nf][0], accf[1][nf][0]);
                accf[1][nf][1] = fmaf(s2, accp[1][nf][1], accf[1][nf][1]);
                accf[1][nf][2] = fmaf(s3, accp[1][nf][2], accf[1][nf][2]);
                accf[1][nf][3] = fmaf(s3, accp[1][nf][3], accf[1][nf][3]);
            }
        }
        __syncthreads();
    }

    // epilogue: fp32 stores rounded through bf16 (c0,c1 -> row g; c2,c3 -> row g+8)
    const int colBase = n0 + (wn << 5) + (cc << 1);
#pragma unroll
    for (int mf = 0; mf < 2; mf++) {
        int r0 = m0 + (wm << 5) + (mf << 4) + g;
        float* p0 = out + (size_t)r0 * N + colBase;
        float* p1 = out + (size_t)(r0 + 8) * N + colBase;
#pragma unroll
        for (int nf = 0; nf < 4; nf++) {
            float2 v0, v1;
            v0.x = __bfloat162float(__float2bfloat16_rn(accf[mf][nf][0]));
            v0.y = __bfloat162float(__float2bfloat16_rn(accf[mf][nf][1]));
            v1.x = __bfloat162float(__float2bfloat16_rn(accf[mf][nf][2]));
            v1.y = __bfloat162float(__float2bfloat16_rn(accf[mf][nf][3]));
            *reinterpret_cast<float2*>(p0 + (nf << 3)) = v0;
            *reinterpret_cast<float2*>(p1 + (nf << 3)) = v1;
        }
    }
}

// ---------------- launch ----------------
extern "C" void kernel_launch(void* const* d_in, const int* in_sizes, int n_in,
                              void* d_out, int out_size) {
    const float* x = (const float*)d_in[0];
    const float* w = (const float*)d_in[1];

    double a = (double)in_sizes[0], b = (double)in_sizes[1], c = (double)out_size;
    int K = (int)llround(sqrt(a * b / c));
    int M = in_sizes[0] / K;
    int N = in_sizes[1] / K;
    int KB = K / 128;

    {
        long long pairs = ((long long)M * KB) >> 1;   // 2 blocks per warp
        int blocks = (int)((pairs + 7) / 8);
        quant_act_kernel<<<blocks, 256>>>(x, M, KB);
    }
    {
        dim3 g(KB, N / 128);
        quant_w_kernel<<<g, 256>>>(w, N, KB);
    }
    {
        cudaFuncSetAttribute(gemm_kernel, cudaFuncAttributeMaxDynamicSharedMemorySize, SMEM_TOTAL);
        dim3 g(N / 64, M / 128);
        gemm_kernel<<<g, 256, SMEM_TOTAL>>>((float*)d_out, M, N, K);
    }
}

// round 14
// speedup vs baseline: 1.0558x; 1.0558x over previous
#include <cuda_runtime.h>
#include <cuda_bf16.h>
#include <cuda_fp16.h>
#include <cuda_fp8.h>
#include <cstdint>
#include <math.h>

#define DINLINE __device__ __forceinline__

// ---------------- static scratch (no allocations allowed) ----------------
#define MAXM 16384
#define MAXK 2048
#define MAXN 2048
__device__ uint8_t g_aq[(size_t)MAXM * MAXK];            // quantized activations, raw e4m3 bytes
__device__ float   g_as[(size_t)MAXM * (MAXK/128)];
__device__ uint8_t g_wq[(size_t)MAXN * MAXK];            // quantized weights, raw e4m3 bytes
__device__ float   g_ws[(size_t)(MAXN/128) * (MAXK/128)];

// ---------------- helpers ----------------
DINLINE uint32_t smem_u32(const void* p) {
    uint32_t a;
    asm("{ .reg .u64 t; cvta.to.shared.u64 t, %1; cvt.u32.u64 %0, t; }" : "=r"(a) : "l"(p));
    return a;
}
DINLINE void cp_async16(uint32_t dst, const void* src) {
    asm volatile("cp.async.cg.shared.global [%0], [%1], 16;" :: "r"(dst), "l"(src));
}
DINLINE void cp_commit() { asm volatile("cp.async.commit_group;" ::: "memory"); }
template <int N> DINLINE void cp_wait_group() {
    asm volatile("cp.async.wait_group %0;" :: "n"(N) : "memory");
}
DINLINE uint32_t lds32(uint32_t addr) {
    uint32_t v;
    asm volatile("ld.shared.b32 %0, [%1];" : "=r"(v) : "r"(addr));
    return v;
}
// fp8 e4m3 x e4m3 -> fp32 MMA, m16n8k32 (baseline PTX since sm_89)
DINLINE void mma_fp8(float* c, const uint32_t* a, uint32_t b0, uint32_t b1) {
    asm volatile(
        "mma.sync.aligned.m16n8k32.row.col.f32.e4m3.e4m3.f32 "
        "{%0,%1,%2,%3}, {%4,%5,%6,%7}, {%8,%9}, {%0,%1,%2,%3};"
        : "+f"(c[0]), "+f"(c[1]), "+f"(c[2]), "+f"(c[3])
        : "r"(a[0]), "r"(a[1]), "r"(a[2]), "r"(a[3]), "r"(b0), "r"(b1));
}

// pack 4 floats -> 4 e4m3 bytes via paired converts (x -> byte 0)  [proven R10]
DINLINE uint32_t fp8_pack4(float x, float y, float z, float w) {
    uint32_t lo = __nv_cvt_float2_to_fp8x2(make_float2(x, y), __NV_SATFINITE, __NV_E4M3);
    uint32_t hi = __nv_cvt_float2_to_fp8x2(make_float2(z, w), __NV_SATFINITE, __NV_E4M3);
    return lo | (hi << 16);
}
DINLINE float amax4(float4 v) {
    return fmaxf(fmaxf(fabsf(v.x), fabsf(v.y)), fmaxf(fabsf(v.z), fabsf(v.w)));
}

// ---------------- kernel 1: rowwise activation quantization, MLP=4 ----------------
// Each 128-K block handled by 8 lanes; each lane loads 16 consecutive floats
// (4 x float4, MLP=4), 3-shuffle amax reduce within the 8-lane group, packs
// 16 e4m3 bytes, one uint4 store. One warp = 4 blocks.
__global__ void quant_act_kernel(const float* __restrict__ x, int M, int KB) {
    int warp = blockIdx.x * (blockDim.x >> 5) + (threadIdx.x >> 5);
    int lane = threadIdx.x & 31;
    int nQuads = (M * KB) >> 2;
    if (warp >= nQuads) return;
    int blk = (warp << 2) + (lane >> 3);     // this 8-lane group's 128-block
    int m = blk / KB, kb = blk - m * KB;
    int K = KB << 7;
    int l = lane & 7;                        // position within block (16 floats)
    const float4* base = reinterpret_cast<const float4*>(x + (size_t)m * K + (kb << 7) + (l << 4));
    float4 v0 = base[0];
    float4 v1 = base[1];
    float4 v2 = base[2];
    float4 v3 = base[3];

    float amax = fmaxf(fmaxf(amax4(v0), amax4(v1)), fmaxf(amax4(v2), amax4(v3)));
#pragma unroll
    for (int o = 4; o > 0; o >>= 1) amax = fmaxf(amax, __shfl_xor_sync(0xffffffffu, amax, o));
    amax = fmaxf(amax, 1e-4f);
    float scale = amax / 448.0f;
    float inv = 1.0f / scale;

    uint4 packed;
    packed.x = fp8_pack4(v0.x * inv, v0.y * inv, v0.z * inv, v0.w * inv);
    packed.y = fp8_pack4(v1.x * inv, v1.y * inv, v1.z * inv, v1.w * inv);
    packed.z = fp8_pack4(v2.x * inv, v2.y * inv, v2.z * inv, v2.w * inv);
    packed.w = fp8_pack4(v3.x * inv, v3.y * inv, v3.z * inv, v3.w * inv);
    *reinterpret_cast<uint4*>(g_aq + (size_t)m * K + (kb << 7) + (l << 4)) = packed;
    if (l == 0) g_as[(size_t)m * KB + kb] = scale;
}

// ---------------- kernel 2: 128x128 blockwise weight quantization (R10 — proven) ----------------
__global__ void quant_w_kernel(const float* __restrict__ w, int N, int KB) {
    int kb = blockIdx.x, nb = blockIdx.y;
    int K = KB << 7;
    int tid = threadIdx.x;  // 256
    const float* base = w + (size_t)(nb * 128) * K + (kb << 7);
    float4 v[16];
    float amax = 0.f;
#pragma unroll
    for (int j = 0; j < 16; j++) {
        int chunk = tid + j * 256;
        int row = chunk >> 5;
        int col4 = chunk & 31;
        v[j] = *reinterpret_cast<const float4*>(base + (size_t)row * K + col4 * 4);
        amax = fmaxf(amax, fmaxf(fmaxf(fabsf(v[j].x), fabsf(v[j].y)),
                                 fmaxf(fabsf(v[j].z), fabsf(v[j].w))));
    }
    __shared__ float red[8];
#pragma unroll
    for (int o = 16; o > 0; o >>= 1) amax = fmaxf(amax, __shfl_xor_sync(0xffffffffu, amax, o));
    if ((tid & 31) == 0) red[tid >> 5] = amax;
    __syncthreads();
    if (tid == 0) {
        float m = red[0];
#pragma unroll
        for (int i = 1; i < 8; i++) m = fmaxf(m, red[i]);
        m = fmaxf(m, 1e-4f);
        float s = m / 448.0f;
        red[0] = s;
        g_ws[(size_t)nb * KB + kb] = s;
    }
    __syncthreads();
    float inv = 1.0f / red[0];
#pragma unroll
    for (int j = 0; j < 16; j++) {
        int chunk = tid + j * 256;
        int row = chunk >> 5;
        int col4 = chunk & 31;
        uint32_t packed = fp8_pack4(v[j].x * inv, v[j].y * inv, v[j].z * inv, v[j].w * inv);
        *reinterpret_cast<uint32_t*>(g_wq + (size_t)(nb * 128 + row) * K + (kb << 7) + col4 * 4) = packed;
    }
}

// ---------------- kernel 3: fp8 mma.sync GEMM — R12 config, byte-identical (best measured) ----------------
// CTA tile 128(M) x 64(N), BK=128 bytes, STAGES=3, smem 82,944 B/CTA,
// 2 CTAs/SM, 8 warps as 4(M) x 2(N), warp tile 32x32.

#define BM 128
#define BN 64
#define BKB 128                                   // K-bytes per iteration
#define STAGES 3
#define RSTRIDE 144
#define TILE_A (128 * RSTRIDE)                    // 18432
#define TILE_B (64 * RSTRIDE)                     // 9216
#define STAGE_BYTES (TILE_A + TILE_B)             // 27648
#define SMEM_TOTAL (STAGES * STAGE_BYTES)         // 82944

DINLINE void load_stage(uint32_t sA, uint32_t sB,
                        const uint8_t* gA, const uint8_t* gB,
                        int K, int tid) {
#pragma unroll
    for (int i = 0; i < 4; i++) {
        int c = tid + i * 256;                 // 1024 chunks of 16B (A: 128 rows)
        int row = c >> 3;
        int cir = c & 7;
        cp_async16(sA + (uint32_t)(row * RSTRIDE + cir * 16),
                   (const void*)(gA + (size_t)row * K + (cir << 4)));
    }
#pragma unroll
    for (int i = 0; i < 2; i++) {
        int c = tid + i * 256;                 // 512 chunks (B: 64 rows)
        int row = c >> 3;
        int cir = c & 7;
        cp_async16(sB + (uint32_t)(row * RSTRIDE + cir * 16),
                   (const void*)(gB + (size_t)row * K + (cir << 4)));
    }
}

__global__ void __launch_bounds__(256, 2)
gemm_kernel(float* __restrict__ out, int M, int N, int K) {
    extern __shared__ __align__(128) unsigned char dynsmem[];
    const int KB  = K >> 7;        // scale blocks == iterations (BK=128)
    const int tid = threadIdx.x;
    const int wid = tid >> 5;
    const int lane = tid & 31;
    const int wm = wid >> 1;       // 0..3  (M)
    const int wn = wid & 1;        // 0..1  (N)
    const int nb = blockIdx.x, mb = blockIdx.y;
    const int m0 = mb << 7, n0 = nb << 6;

    uint32_t sbase = smem_u32(dynsmem);
    const uint8_t* gA = g_aq + (size_t)m0 * K;
    const uint8_t* gB = g_wq + (size_t)n0 * K;

    float accf[2][4][4];
#pragma unroll
    for (int i = 0; i < 2; i++)
#pragma unroll
        for (int j = 0; j < 4; j++)
#pragma unroll
            for (int q = 0; q < 4; q++) accf[i][j][q] = 0.f;

    const int g  = lane >> 2;      // fragment row group 0..7
    const int cc = lane & 3;       // fragment k chunk 0..3 (4 bytes each)
    const uint32_t fragOff = (uint32_t)(g * RSTRIDE + cc * 4);

    uint32_t aBase[2], bBase[4];
#pragma unroll
    for (int mf = 0; mf < 2; mf++) aBase[mf] = (uint32_t)(((wm << 5) + (mf << 4)) * RSTRIDE) + fragOff;
#pragma unroll
    for (int nf = 0; nf < 4; nf++) bBase[nf] = (uint32_t)(((wn << 5) + (nf << 3)) * RSTRIDE) + fragOff;

    // prologue: fill stages 0, 1
#pragma unroll
    for (int s = 0; s < STAGES - 1; s++) {
        load_stage(sbase + s * STAGE_BYTES, sbase + s * STAGE_BYTES + TILE_A,
                   gA + (size_t)s * BKB, gB + (size_t)s * BKB, K, tid);
        cp_commit();
    }

    const float* wsp = g_ws + (size_t)(n0 >> 7) * KB;
    const int rA0 = m0 + (wm << 5) + g;

    int cur = 0;                    // stage being computed
    int pfs = STAGES - 1;           // stage being prefetched

    for (int it = 0; it < KB; ++it) {
        cp_wait_group<STAGES - 2>();
        __syncthreads();

        int pf = it + STAGES - 1;
        if (pf < KB) {
            load_stage(sbase + pfs * STAGE_BYTES, sbase + pfs * STAGE_BYTES + TILE_A,
                       gA + (size_t)pf * BKB, gB + (size_t)pf * BKB, K, tid);
        }
        cp_commit();
        if (++pfs == STAGES) pfs = 0;

        uint32_t stA = sbase + cur * STAGE_BYTES;
        uint32_t stB = stA + TILE_A;
        if (++cur == STAGES) cur = 0;

        float accp[2][4][4];
#pragma unroll
        for (int i = 0; i < 2; i++)
#pragma unroll
            for (int j = 0; j < 4; j++)
#pragma unroll
                for (int q = 0; q < 4; q++) accp[i][j][q] = 0.f;

#pragma unroll
        for (int kk = 0; kk < 4; kk++) {               // 4 x k32 = 128 K-bytes
            const uint32_t kOff = (uint32_t)(kk * 32);
            uint32_t a[2][4];
#pragma unroll
            for (int mf = 0; mf < 2; mf++) {
                uint32_t p = stA + aBase[mf] + kOff;
                a[mf][0] = lds32(p);                    // A[g   ][4c..4c+3]
                a[mf][1] = lds32(p + 8 * RSTRIDE);      // A[g+8 ][4c..4c+3]
                a[mf][2] = lds32(p + 16);               // A[g   ][16+4c..]
                a[mf][3] = lds32(p + 8 * RSTRIDE + 16); // A[g+8 ][16+4c..]
            }
            uint32_t b[4][2];
#pragma unroll
            for (int nf = 0; nf < 4; nf++) {
                uint32_t p = stB + bBase[nf] + kOff;
                b[nf][0] = lds32(p);                    // W[n][4c..4c+3]
                b[nf][1] = lds32(p + 16);               // W[n][16+4c..]
            }
#pragma unroll
            for (int mf = 0; mf < 2; mf++)
#pragma unroll
                for (int nf = 0; nf < 4; nf++)
                    mma_fp8(accp[mf][nf], a[mf], b[nf][0], b[nf][1]);
        }

        // promote this 128-K block: accf += (a_s[row]*w_s) * accp
        {
            float ws = __ldg(wsp + it);
#pragma unroll
            for (int mf = 0; mf < 2; mf++) {
                float s0 = __ldg(g_as + (size_t)(rA0 + (mf << 4)) * KB + it) * ws;
                float s1 = __ldg(g_as + (size_t)(rA0 + (mf << 4) + 8) * KB + it) * ws;
#pragma unroll
                for (int nf = 0; nf < 4; nf++) {
                    accf[mf][nf][0] = fmaf(s0, accp[mf][nf][0], accf[mf][nf][0]);
                    accf[mf][nf][1] = fmaf(s0, accp[mf][nf][1], accf[mf][nf][1]);
                    accf[mf][nf][2] = fmaf(s1, accp[mf][nf][2], accf[mf][nf][2]);
                    accf[mf][nf][3] = fmaf(s1, accp[mf][nf][3], accf[mf][nf][3]);
                }
            }
        }
        __syncthreads();
    }

    // epilogue: fp32 stores rounded through bf16 (c0,c1 -> row g; c2,c3 -> row g+8)
    const int colBase = n0 + (wn << 5) + (cc << 1);
#pragma unroll
    for (int mf = 0; mf < 2; mf++) {
        int r0 = m0 + (wm << 5) + (mf << 4) + g;
        float* p0 = out + (size_t)r0 * N + colBase;
        float* p1 = out + (size_t)(r0 + 8) * N + colBase;
#pragma unroll
        for (int nf = 0; nf < 4; nf++) {
            float2 v0, v1;
            v0.x = __bfloat162float(__float2bfloat16_rn(accf[mf][nf][0]));
            v0.y = __bfloat162float(__float2bfloat16_rn(accf[mf][nf][1]));
            v1.x = __bfloat162float(__float2bfloat16_rn(accf[mf][nf][2]));
            v1.y = __bfloat162float(__float2bfloat16_rn(accf[mf][nf][3]));
            *reinterpret_cast<float2*>(p0 + (nf << 3)) = v0;
            *reinterpret_cast<float2*>(p1 + (nf << 3)) = v1;
        }
    }
}

// ---------------- launch ----------------
extern "C" void kernel_launch(void* const* d_in, const int* in_sizes, int n_in,
                              void* d_out, int out_size) {
    const float* x = (const float*)d_in[0];
    const float* w = (const float*)d_in[1];

    double a = (double)in_sizes[0], b = (double)in_sizes[1], c = (double)out_size;
    int K = (int)llround(sqrt(a * b / c));
    int M = in_sizes[0] / K;
    int N = in_sizes[1] / K;
    int KB = K / 128;

    {
        long long quads = ((long long)M * KB) >> 2;   // 4 blocks per warp
        int blocks = (int)((quads + 7) / 8);
        quant_act_kernel<<<blocks, 256>>>(x, M, KB);
    }
    {
        dim3 g(KB, N / 128);
        quant_w_kernel<<<g, 256>>>(w, N, KB);
    }
    {
        cudaFuncSetAttribute(gemm_kernel, cudaFuncAttributeMaxDynamicSharedMemorySize, SMEM_TOTAL);
        dim3 g(N / 64, M / 128);
        gemm_kernel<<<g, 256, SMEM_TOTAL>>>((float*)d_out, M, N, K);
    }
}

// round 15
// speedup vs baseline: 1.0574x; 1.0016x over previous
#include <cuda_runtime.h>
#include <cuda_bf16.h>
#include <cuda_fp16.h>
#include <cuda_fp8.h>
#include <cstdint>
#include <math.h>

#define DINLINE __device__ __forceinline__

// ---------------- static scratch (no allocations allowed) ----------------
#define MAXM 16384
#define MAXK 2048
#define MAXN 2048
__device__ uint8_t g_aq[(size_t)MAXM * MAXK];            // quantized activations, raw e4m3 bytes
__device__ float   g_as[(size_t)MAXM * (MAXK/128)];
__device__ uint8_t g_wq[(size_t)MAXN * MAXK];            // quantized weights, raw e4m3 bytes
__device__ float   g_ws[(size_t)(MAXN/128) * (MAXK/128)];

// ---------------- helpers ----------------
DINLINE uint32_t smem_u32(const void* p) {
    uint32_t a;
    asm("{ .reg .u64 t; cvta.to.shared.u64 t, %1; cvt.u32.u64 %0, t; }" : "=r"(a) : "l"(p));
    return a;
}
DINLINE void cp_async16(uint32_t dst, const void* src) {
    asm volatile("cp.async.cg.shared.global [%0], [%1], 16;" :: "r"(dst), "l"(src));
}
DINLINE void cp_commit() { asm volatile("cp.async.commit_group;" ::: "memory"); }
template <int N> DINLINE void cp_wait_group() {
    asm volatile("cp.async.wait_group %0;" :: "n"(N) : "memory");
}
DINLINE uint32_t lds32(uint32_t addr) {
    uint32_t v;
    asm volatile("ld.shared.b32 %0, [%1];" : "=r"(v) : "r"(addr));
    return v;
}
// fp8 e4m3 x e4m3 -> fp32 MMA, m16n8k32 (baseline PTX since sm_89)
DINLINE void mma_fp8(float* c, const uint32_t* a, uint32_t b0, uint32_t b1) {
    asm volatile(
        "mma.sync.aligned.m16n8k32.row.col.f32.e4m3.e4m3.f32 "
        "{%0,%1,%2,%3}, {%4,%5,%6,%7}, {%8,%9}, {%0,%1,%2,%3};"
        : "+f"(c[0]), "+f"(c[1]), "+f"(c[2]), "+f"(c[3])
        : "r"(a[0]), "r"(a[1]), "r"(a[2]), "r"(a[3]), "r"(b0), "r"(b1));
}

// pack 4 floats -> 4 e4m3 bytes via paired converts (x -> byte 0)  [proven R10]
DINLINE uint32_t fp8_pack4(float x, float y, float z, float w) {
    uint32_t lo = __nv_cvt_float2_to_fp8x2(make_float2(x, y), __NV_SATFINITE, __NV_E4M3);
    uint32_t hi = __nv_cvt_float2_to_fp8x2(make_float2(z, w), __NV_SATFINITE, __NV_E4M3);
    return lo | (hi << 16);
}
DINLINE float amax4(float4 v) {
    return fmaxf(fmaxf(fabsf(v.x), fabsf(v.y)), fmaxf(fabsf(v.z), fabsf(v.w)));
}

// ---------------- kernel 1: rowwise activation quantization, MLP=4, line-coalesced ----------------
// Each 128-K block handled by 8 lanes. Lane l takes 16B chunks {l, l+8, l+16,
// l+24} of the block's 32 chunks: every LDG.128 instruction covers whole 128B
// lines (4 lines/warp = HW minimum), vs 16 lines with consecutive-chunk
// assignment. Same element set per block -> scale and bytes bit-identical.
__global__ void quant_act_kernel(const float* __restrict__ x, int M, int KB) {
    int warp = blockIdx.x * (blockDim.x >> 5) + (threadIdx.x >> 5);
    int lane = threadIdx.x & 31;
    int nQuads = (M * KB) >> 2;
    if (warp >= nQuads) return;
    int blk = (warp << 2) + (lane >> 3);     // this 8-lane group's 128-block
    int m = blk / KB, kb = blk - m * KB;
    int K = KB << 7;
    int l = lane & 7;                        // chunk lane 0..7
    const float4* base = reinterpret_cast<const float4*>(x + (size_t)m * K + (kb << 7)) + l;
    float4 v0 = base[0];                     // chunk l
    float4 v1 = base[8];                     // chunk l+8
    float4 v2 = base[16];                    // chunk l+16
    float4 v3 = base[24];                    // chunk l+24

    float amax = fmaxf(fmaxf(amax4(v0), amax4(v1)), fmaxf(amax4(v2), amax4(v3)));
#pragma unroll
    for (int o = 4; o > 0; o >>= 1) amax = fmaxf(amax, __shfl_xor_sync(0xffffffffu, amax, o));
    amax = fmaxf(amax, 1e-4f);
    float scale = amax / 448.0f;
    float inv = 1.0f / scale;

    uint32_t* dst = reinterpret_cast<uint32_t*>(g_aq + (size_t)m * K + (kb << 7)) + l;
    dst[0]  = fp8_pack4(v0.x * inv, v0.y * inv, v0.z * inv, v0.w * inv);
    dst[8]  = fp8_pack4(v1.x * inv, v1.y * inv, v1.z * inv, v1.w * inv);
    dst[16] = fp8_pack4(v2.x * inv, v2.y * inv, v2.z * inv, v2.w * inv);
    dst[24] = fp8_pack4(v3.x * inv, v3.y * inv, v3.z * inv, v3.w * inv);
    if (l == 0) g_as[(size_t)m * KB + kb] = scale;
}

// ---------------- kernel 2: 128x128 blockwise weight quantization (R10 — proven) ----------------
__global__ void quant_w_kernel(const float* __restrict__ w, int N, int KB) {
    int kb = blockIdx.x, nb = blockIdx.y;
    int K = KB << 7;
    int tid = threadIdx.x;  // 256
    const float* base = w + (size_t)(nb * 128) * K + (kb << 7);
    float4 v[16];
    float amax = 0.f;
#pragma unroll
    for (int j = 0; j < 16; j++) {
        int chunk = tid + j * 256;
        int row = chunk >> 5;
        int col4 = chunk & 31;
        v[j] = *reinterpret_cast<const float4*>(base + (size_t)row * K + col4 * 4);
        amax = fmaxf(amax, fmaxf(fmaxf(fabsf(v[j].x), fabsf(v[j].y)),
                                 fmaxf(fabsf(v[j].z), fabsf(v[j].w))));
    }
    __shared__ float red[8];
#pragma unroll
    for (int o = 16; o > 0; o >>= 1) amax = fmaxf(amax, __shfl_xor_sync(0xffffffffu, amax, o));
    if ((tid & 31) == 0) red[tid >> 5] = amax;
    __syncthreads();
    if (tid == 0) {
        float m = red[0];
#pragma unroll
        for (int i = 1; i < 8; i++) m = fmaxf(m, red[i]);
        m = fmaxf(m, 1e-4f);
        float s = m / 448.0f;
        red[0] = s;
        g_ws[(size_t)nb * KB + kb] = s;
    }
    __syncthreads();
    float inv = 1.0f / red[0];
#pragma unroll
    for (int j = 0; j < 16; j++) {
        int chunk = tid + j * 256;
        int row = chunk >> 5;
        int col4 = chunk & 31;
        uint32_t packed = fp8_pack4(v[j].x * inv, v[j].y * inv, v[j].z * inv, v[j].w * inv);
        *reinterpret_cast<uint32_t*>(g_wq + (size_t)(nb * 128 + row) * K + (kb << 7) + col4 * 4) = packed;
    }
}

// ---------------- kernel 3: fp8 mma.sync GEMM — R12 config, byte-identical (saturated; best measured) ----------------
#define BM 128
#define BN 64
#define BKB 128                                   // K-bytes per iteration
#define STAGES 3
#define RSTRIDE 144
#define TILE_A (128 * RSTRIDE)                    // 18432
#define TILE_B (64 * RSTRIDE)                     // 9216
#define STAGE_BYTES (TILE_A + TILE_B)             // 27648
#define SMEM_TOTAL (STAGES * STAGE_BYTES)         // 82944

DINLINE void load_stage(uint32_t sA, uint32_t sB,
                        const uint8_t* gA, const uint8_t* gB,
                        int K, int tid) {
#pragma unroll
    for (int i = 0; i < 4; i++) {
        int c = tid + i * 256;                 // 1024 chunks of 16B (A: 128 rows)
        int row = c >> 3;
        int cir = c & 7;
        cp_async16(sA + (uint32_t)(row * RSTRIDE + cir * 16),
                   (const void*)(gA + (size_t)row * K + (cir << 4)));
    }
#pragma unroll
    for (int i = 0; i < 2; i++) {
        int c = tid + i * 256;                 // 512 chunks (B: 64 rows)
        int row = c >> 3;
        int cir = c & 7;
        cp_async16(sB + (uint32_t)(row * RSTRIDE + cir * 16),
                   (const void*)(gB + (size_t)row * K + (cir << 4)));
    }
}

__global__ void __launch_bounds__(256, 2)
gemm_kernel(float* __restrict__ out, int M, int N, int K) {
    extern __shared__ __align__(128) unsigned char dynsmem[];
    const int KB  = K >> 7;        // scale blocks == iterations (BK=128)
    const int tid = threadIdx.x;
    const int wid = tid >> 5;
    const int lane = tid & 31;
    const int wm = wid >> 1;       // 0..3  (M)
    const int wn = wid & 1;        // 0..1  (N)
    const int nb = blockIdx.x, mb = blockIdx.y;
    const int m0 = mb << 7, n0 = nb << 6;

    uint32_t sbase = smem_u32(dynsmem);
    const uint8_t* gA = g_aq + (size_t)m0 * K;
    const uint8_t* gB = g_wq + (size_t)n0 * K;

    float accf[2][4][4];
#pragma unroll
    for (int i = 0; i < 2; i++)
#pragma unroll
        for (int j = 0; j < 4; j++)
#pragma unroll
            for (int q = 0; q < 4; q++) accf[i][j][q] = 0.f;

    const int g  = lane >> 2;      // fragment row group 0..7
    const int cc = lane & 3;       // fragment k chunk 0..3 (4 bytes each)
    const uint32_t fragOff = (uint32_t)(g * RSTRIDE + cc * 4);

    uint32_t aBase[2], bBase[4];
#pragma unroll
    for (int mf = 0; mf < 2; mf++) aBase[mf] = (uint32_t)(((wm << 5) + (mf << 4)) * RSTRIDE) + fragOff;
#pragma unroll
    for (int nf = 0; nf < 4; nf++) bBase[nf] = (uint32_t)(((wn << 5) + (nf << 3)) * RSTRIDE) + fragOff;

    // prologue: fill stages 0, 1
#pragma unroll
    for (int s = 0; s < STAGES - 1; s++) {
        load_stage(sbase + s * STAGE_BYTES, sbase + s * STAGE_BYTES + TILE_A,
                   gA + (size_t)s * BKB, gB + (size_t)s * BKB, K, tid);
        cp_commit();
    }

    const float* wsp = g_ws + (size_t)(n0 >> 7) * KB;
    const int rA0 = m0 + (wm << 5) + g;

    int cur = 0;                    // stage being computed
    int pfs = STAGES - 1;           // stage being prefetched

    for (int it = 0; it < KB; ++it) {
        cp_wait_group<STAGES - 2>();
        __syncthreads();

        int pf = it + STAGES - 1;
        if (pf < KB) {
            load_stage(sbase + pfs * STAGE_BYTES, sbase + pfs * STAGE_BYTES + TILE_A,
                       gA + (size_t)pf * BKB, gB + (size_t)pf * BKB, K, tid);
        }
        cp_commit();
        if (++pfs == STAGES) pfs = 0;

        uint32_t stA = sbase + cur * STAGE_BYTES;
        uint32_t stB = stA + TILE_A;
        if (++cur == STAGES) cur = 0;

        float accp[2][4][4];
#pragma unroll
        for (int i = 0; i < 2; i++)
#pragma unroll
            for (int j = 0; j < 4; j++)
#pragma unroll
                for (int q = 0; q < 4; q++) accp[i][j][q] = 0.f;

#pragma unroll
        for (int kk = 0; kk < 4; kk++) {               // 4 x k32 = 128 K-bytes
            const uint32_t kOff = (uint32_t)(kk * 32);
            uint32_t a[2][4];
#pragma unroll
            for (int mf = 0; mf < 2; mf++) {
                uint32_t p = stA + aBase[mf] + kOff;
                a[mf][0] = lds32(p);                    // A[g   ][4c..4c+3]
                a[mf][1] = lds32(p + 8 * RSTRIDE);      // A[g+8 ][4c..4c+3]
                a[mf][2] = lds32(p + 16);               // A[g   ][16+4c..]
                a[mf][3] = lds32(p + 8 * RSTRIDE + 16); // A[g+8 ][16+4c..]
            }
            uint32_t b[4][2];
#pragma unroll
            for (int nf = 0; nf < 4; nf++) {
                uint32_t p = stB + bBase[nf] + kOff;
                b[nf][0] = lds32(p);                    // W[n][4c..4c+3]
                b[nf][1] = lds32(p + 16);               // W[n][16+4c..]
            }
#pragma unroll
            for (int mf = 0; mf < 2; mf++)
#pragma unroll
                for (int nf = 0; nf < 4; nf++)
                    mma_fp8(accp[mf][nf], a[mf], b[nf][0], b[nf][1]);
        }

        // promote this 128-K block: accf += (a_s[row]*w_s) * accp
        {
            float ws = __ldg(wsp + it);
#pragma unroll
            for (int mf = 0; mf < 2; mf++) {
                float s0 = __ldg(g_as + (size_t)(rA0 + (mf << 4)) * KB + it) * ws;
                float s1 = __ldg(g_as + (size_t)(rA0 + (mf << 4) + 8) * KB + it) * ws;
#pragma unroll
                for (int nf = 0; nf < 4; nf++) {
                    accf[mf][nf][0] = fmaf(s0, accp[mf][nf][0], accf[mf][nf][0]);
                    accf[mf][nf][1] = fmaf(s0, accp[mf][nf][1], accf[mf][nf][1]);
                    accf[mf][nf][2] = fmaf(s1, accp[mf][nf][2], accf[mf][nf][2]);
                    accf[mf][nf][3] = fmaf(s1, accp[mf][nf][3], accf[mf][nf][3]);
                }
            }
        }
        __syncthreads();
    }

    // epilogue: fp32 stores rounded through bf16 (c0,c1 -> row g; c2,c3 -> row g+8)
    const int colBase = n0 + (wn << 5) + (cc << 1);
#pragma unroll
    for (int mf = 0; mf < 2; mf++) {
        int r0 = m0 + (wm << 5) + (mf << 4) + g;
        float* p0 = out + (size_t)r0 * N + colBase;
        float* p1 = out + (size_t)(r0 + 8) * N + colBase;
#pragma unroll
        for (int nf = 0; nf < 4; nf++) {
            float2 v0, v1;
            v0.x = __bfloat162float(__float2bfloat16_rn(accf[mf][nf][0]));
            v0.y = __bfloat162float(__float2bfloat16_rn(accf[mf][nf][1]));
            v1.x = __bfloat162float(__float2bfloat16_rn(accf[mf][nf][2]));
            v1.y = __bfloat162float(__float2bfloat16_rn(accf[mf][nf][3]));
            *reinterpret_cast<float2*>(p0 + (nf << 3)) = v0;
            *reinterpret_cast<float2*>(p1 + (nf << 3)) = v1;
        }
    }
}

// ---------------- launch ----------------
extern "C" void kernel_launch(void* const* d_in, const int* in_sizes, int n_in,
                              void* d_out, int out_size) {
    const float* x = (const float*)d_in[0];
    const float* w = (const float*)d_in[1];

    double a = (double)in_sizes[0], b = (double)in_sizes[1], c = (double)out_size;
    int K = (int)llround(sqrt(a * b / c));
    int M = in_sizes[0] / K;
    int N = in_sizes[1] / K;
    int KB = K / 128;

    {
        long long quads = ((long long)M * KB) >> 2;   // 4 blocks per warp
        int blocks = (int)((quads + 7) / 8);
        quant_act_kernel<<<blocks, 256>>>(x, M, KB);
    }
    {
        dim3 g(KB, N / 128);
        quant_w_kernel<<<g, 256>>>(w, N, KB);
    }
    {
        cudaFuncSetAttribute(gemm_kernel, cudaFuncAttributeMaxDynamicSharedMemorySize, SMEM_TOTAL);
        dim3 g(N / 64, M / 128);
        gemm_kernel<<<g, 256, SMEM_TOTAL>>>((float*)d_out, M, N, K);
    }
}